// round 11
// baseline (speedup 1.0000x reference)
#include <cuda_runtime.h>
#include <cuda_bf16.h>
#include <stdint.h>

// ======================= fragment-packed weight image (R8-proven) =======================
#define OFF_B1    0
#define OFF_B0    28672
#define OFF_B1B   36864
#define OFF_BIAS1 40960
#define OFF_B0F   43008
#define OFF_B1F   44032
#define OFF_W2F   45056
#define OFF_B2    47104
#define PACK_BYTES 47120

__device__ __align__(16) unsigned char g_pack[PACK_BYTES];

// ======================= helpers =======================
__device__ __forceinline__ uint32_t pack_bf16x2(float a, float b) {
    __nv_bfloat16 ha = __float2bfloat16(a), hb = __float2bfloat16(b);
    return (uint32_t)__bfloat16_as_ushort(ha) | ((uint32_t)__bfloat16_as_ushort(hb) << 16);
}
__device__ __forceinline__ void bsplit(float f, float& h, float& l) {
    __nv_bfloat16 hb = __float2bfloat16(f);
    h = __bfloat162float(hb);
    l = f - h;
}
// trunc split: hi = f masked to bf16 bits (exact residual), lo = rn-bf16 of residual
__device__ __forceinline__ void split_pack2_fast(float f0, float f1, uint32_t& hr, uint32_t& lr) {
    uint32_t u0 = __float_as_uint(f0), u1 = __float_as_uint(f1);
    float h0 = __uint_as_float(u0 & 0xFFFF0000u);
    float h1 = __uint_as_float(u1 & 0xFFFF0000u);
    float l0 = f0 - h0;
    float l1 = f1 - h1;
    asm("prmt.b32 %0, %1, %2, 0x7632;" : "=r"(hr) : "r"(u0), "r"(u1));
    asm("cvt.rn.bf16x2.f32 %0, %1, %2;" : "=r"(lr) : "f"(l1), "f"(l0));
}
__device__ __forceinline__ void mma16816(float* c, const uint32_t* a, uint32_t b0, uint32_t b1) {
    asm volatile(
        "mma.sync.aligned.m16n8k16.row.col.f32.bf16.bf16.f32 "
        "{%0,%1,%2,%3}, {%4,%5,%6,%7}, {%8,%9}, {%0,%1,%2,%3};"
        : "+f"(c[0]), "+f"(c[1]), "+f"(c[2]), "+f"(c[3])
        : "r"(a[0]), "r"(a[1]), "r"(a[2]), "r"(a[3]), "r"(b0), "r"(b1));
}

// ======================= prep kernel (unchanged from R8) =======================
__device__ __forceinline__ float getW1c(const float* Ww, const float* Wb, int n, int k) {
    if (k >= 98) return 0.f;
    if (n < 32) return Ww[n * 98 + k];
    int kk = k + 49; if (kk >= 98) kk -= 98;
    return Wb[(n - 32) * 98 + kk];
}

__global__ void prep_kernel(const float* __restrict__ Ww, const float* __restrict__ Wb,
                            const float* __restrict__ W0, const float* __restrict__ W1,
                            const float* __restrict__ bw, const float* __restrict__ bb,
                            const float* __restrict__ b0, const float* __restrict__ b1,
                            const float* __restrict__ W2, const float* __restrict__ b2)
{
    const int tid = threadIdx.x;  // 256 threads
    char* gp = (char*)g_pack;

    for (int idx = tid; idx < 8 * 7 * 32; idx += 256) {
        int lane = idx & 31, t = idx >> 5;
        int kt = t % 7, nt = t / 7;
        int n = nt * 8 + (lane >> 2);
        int k0 = kt * 16 + (lane & 3) * 2;
        float w[4] = { getW1c(Ww, Wb, n, k0),     getW1c(Ww, Wb, n, k0 + 1),
                       getW1c(Ww, Wb, n, k0 + 8), getW1c(Ww, Wb, n, k0 + 9) };
        float h[4], l[4];
        for (int i = 0; i < 4; i++) bsplit(w[i], h[i], l[i]);
        uint4 v;
        v.x = pack_bf16x2(h[0], h[1]); v.y = pack_bf16x2(h[2], h[3]);
        v.z = pack_bf16x2(l[0], l[1]); v.w = pack_bf16x2(l[2], l[3]);
        ((uint4*)(gp + OFF_B1))[idx] = v;
    }
    for (int idx = tid; idx < 4 * 4 * 32; idx += 256) {
        int lane = idx & 31, t = idx >> 5;
        int kt = t & 3, nt = t >> 2;
        int n = nt * 8 + (lane >> 2);
        int k0 = kt * 16 + (lane & 3) * 2;
        float w[4] = { W0[n * 64 + k0],     W0[n * 64 + k0 + 1],
                       W0[n * 64 + k0 + 8], W0[n * 64 + k0 + 9] };
        float h[4], l[4];
        for (int i = 0; i < 4; i++) bsplit(w[i], h[i], l[i]);
        uint4 v;
        v.x = pack_bf16x2(h[0], h[1]); v.y = pack_bf16x2(h[2], h[3]);
        v.z = pack_bf16x2(l[0], l[1]); v.w = pack_bf16x2(l[2], l[3]);
        ((uint4*)(gp + OFF_B0))[idx] = v;
    }
    for (int idx = tid; idx < 4 * 2 * 32; idx += 256) {
        int lane = idx & 31, t = idx >> 5;
        int kt = t & 1, nt = t >> 1;
        int n = nt * 8 + (lane >> 2);
        int k0 = kt * 16 + (lane & 3) * 2;
        float w[4] = { W1[n * 32 + k0],     W1[n * 32 + k0 + 1],
                       W1[n * 32 + k0 + 8], W1[n * 32 + k0 + 9] };
        float h[4], l[4];
        for (int i = 0; i < 4; i++) bsplit(w[i], h[i], l[i]);
        uint4 v;
        v.x = pack_bf16x2(h[0], h[1]); v.y = pack_bf16x2(h[2], h[3]);
        v.z = pack_bf16x2(l[0], l[1]); v.w = pack_bf16x2(l[2], l[3]);
        ((uint4*)(gp + OFF_B1B))[idx] = v;
    }
    for (int idx = tid; idx < 4 * 32; idx += 256) {
        int lane = idx & 31, j = idx >> 5;
        int c = j * 8 + (lane & 3) * 2;
        float4 bf; bf.x = bw[c]; bf.y = bw[c + 1]; bf.z = bb[c]; bf.w = bb[c + 1];
        ((float4*)(gp + OFF_BIAS1))[idx] = bf;
        float2 f0; f0.x = b0[c]; f0.y = b0[c + 1];
        ((float2*)(gp + OFF_B0F))[idx] = f0;
        float2 f1; f1.x = b1[c]; f1.y = b1[c + 1];
        ((float2*)(gp + OFF_B1F))[idx] = f1;
        float4 w2; w2.x = W2[c]; w2.y = W2[c + 1]; w2.z = W2[32 + c]; w2.w = W2[32 + c + 1];
        ((float4*)(gp + OFF_W2F))[idx] = w2;
    }
    if (tid == 0) *((float*)(gp + OFF_B2)) = b2[0];
}

// ======================= main fused kernel =======================
// 256 threads (8 warps), 256 rows/CTA, 2 passes of 128 staged rows.
// Staged plane holds PRE-SPLIT (hi,lo) bf16x2 pair-words: uint2 per column-pair.
// Row stride 60 uint2 (=120 words) -> LDS.64 bank = (24q + 2qp + 16kt) mod 32, conflict-free.
// smem: [pack 47120][plane 128*120*4 = 61440][spov 1024] = 109584 B -> 2 CTAs/SM.
#define NT 256
#define ROWS_CTA 256
#define STAGE_ROWS 128
#define PPR 60                                          // uint2 pairs per row
#define OFF_PLANE  PACK_BYTES                           // 47120
#define OFF_POV    (OFF_PLANE + STAGE_ROWS * PPR * 8)   // 108560
#define SMEM_BYTES (OFF_POV + ROWS_CTA * 4 + 16)        // 109600

__global__ void __launch_bounds__(NT, 2)
nnue_main(const float* __restrict__ pov, const float* __restrict__ white,
          const float* __restrict__ black, float* __restrict__ out, int Btot)
{
    extern __shared__ __align__(16) unsigned char smem[];
    unsigned char* packS = smem;
    uint2* plane = (uint2*)(smem + OFF_PLANE);
    float* spov  = (float*)(smem + OFF_POV);

    const int tid  = threadIdx.x;
    const int warp = tid >> 5;
    const int lane = tid & 31;
    const int q    = lane >> 2;
    const int qp   = lane & 3;
    const long long cbase = (long long)blockIdx.x * ROWS_CTA;

    // ---- copy weight pack into smem (once) ----
    {
        const uint4* src = (const uint4*)g_pack;
        uint4* dst = (uint4*)packS;
        #pragma unroll 4
        for (int i = tid; i < PACK_BYTES / 16; i += NT) dst[i] = src[i];
    }
    spov[tid] = (cbase + tid < (long long)Btot) ? __ldcs(pov + cbase + tid) : 0.f;

    const uint4*  B1u  = (const uint4*)(packS + OFF_B1);
    const uint4*  B0u  = (const uint4*)(packS + OFF_B0);
    const uint4*  B1bu = (const uint4*)(packS + OFF_B1B);
    const float4* bia1 = (const float4*)(packS + OFF_BIAS1);
    const float2* b0f  = (const float2*)(packS + OFF_B0F);
    const float2* b1f  = (const float2*)(packS + OFF_B1F);
    const float4* w2f  = (const float4*)(packS + OFF_W2F);

    #pragma unroll 1
    for (int pass = 0; pass < 2; pass++) {
        const long long pbase = cbase + pass * STAGE_ROWS;
        if (pass > 0) __syncthreads();

        // ---- zero pairs 49..59 of every staged row ----
        for (int i = tid; i < STAGE_ROWS * 11; i += NT) {
            int s = i / 11, pp = 49 + (i - s * 11);
            plane[s * PPR + pp] = make_uint2(0u, 0u);
        }
        // ---- stage 128 rows, PRE-SPLIT into (hi,lo) bf16x2 pair-words ----
        if (pbase + STAGE_ROWS <= (long long)Btot) {
            const float* gw = white + pbase * 49;
            const float* gb = black + pbase * 49;
            #pragma unroll 2
            for (int i = tid; i < STAGE_ROWS * 49; i += NT) {
                int s = i / 49, p = i - s * 49;
                int e0 = 2 * p, e1 = e0 + 1;
                float f0 = (e0 < 49) ? __ldcs(gw + s * 49 + e0) : __ldcs(gb + s * 49 + e0 - 49);
                float f1 = (e1 < 49) ? __ldcs(gw + s * 49 + e1) : __ldcs(gb + s * 49 + e1 - 49);
                uint32_t hi, lo;
                split_pack2_fast(f0, f1, hi, lo);
                plane[s * PPR + p] = make_uint2(hi, lo);
            }
        } else {
            for (int i = tid; i < STAGE_ROWS * 49; i += NT) {
                int s = i / 49, p = i - s * 49;
                long long row = pbase + s;
                float f0 = 0.f, f1 = 0.f;
                if (row < (long long)Btot) {
                    int e0 = 2 * p, e1 = e0 + 1;
                    f0 = (e0 < 49) ? white[row * 49 + e0] : black[row * 49 + e0 - 49];
                    f1 = (e1 < 49) ? white[row * 49 + e1] : black[row * 49 + e1 - 49];
                }
                uint32_t hi, lo;
                split_pack2_fast(f0, f1, hi, lo);
                plane[s * PPR + p] = make_uint2(hi, lo);
            }
        }
        __syncthreads();

        // ---- this warp's m16 tile: local rows warp*16 + q, + 8 ----
        const uint2* r0 = plane + (warp * 16 + q) * PPR;
        const uint2* r1 = r0 + 8 * PPR;

        // ================= layer 1 (A frags: pure LDS.64, zero arithmetic) =================
        float cw[4][4], cb[4][4];
        #pragma unroll
        for (int j = 0; j < 4; j++)
            #pragma unroll
            for (int i = 0; i < 4; i++) { cw[j][i] = 0.f; cb[j][i] = 0.f; }

        #pragma unroll
        for (int kt = 0; kt < 7; kt++) {
            const int wi = kt * 8 + qp;
            uint32_t ah[4], al[4];
            uint2 v;
            v = r0[wi];     ah[0] = v.x; al[0] = v.y;
            v = r1[wi];     ah[1] = v.x; al[1] = v.y;
            v = r0[wi + 4]; ah[2] = v.x; al[2] = v.y;
            v = r1[wi + 4]; ah[3] = v.x; al[3] = v.y;
            #pragma unroll
            for (int j = 0; j < 4; j++) {
                uint4 Bw = B1u[(j * 7 + kt) * 32 + lane];
                uint4 Bb = B1u[((j + 4) * 7 + kt) * 32 + lane];
                mma16816(cw[j], ah, Bw.x, Bw.y);
                mma16816(cw[j], al, Bw.x, Bw.y);
                mma16816(cw[j], ah, Bw.z, Bw.w);
                mma16816(cb[j], ah, Bb.x, Bb.y);
                mma16816(cb[j], al, Bb.x, Bb.y);
                mma16816(cb[j], ah, Bb.z, Bb.w);
            }
        }

        // ---- epilogue 1: bias + pov mix + relu -> layer-0 A frags ----
        const int prow = pass * STAGE_ROWS + warp * 16 + q;
        float pv0 = spov[prow];
        float pv1 = spov[prow + 8];
        float pm0 = 1.f - pv0, pm1 = 1.f - pv1;

        uint32_t a0h[4][4], a0l[4][4];
        #pragma unroll
        for (int j = 0; j < 4; j++) {
            float4 bi = bia1[j * 32 + lane];
            float w0 = cw[j][0] + bi.x, w1 = cw[j][1] + bi.y;
            float w2_ = cw[j][2] + bi.x, w3 = cw[j][3] + bi.y;
            float bb0 = cb[j][0] + bi.z, bb1 = cb[j][1] + bi.w;
            float bb2 = cb[j][2] + bi.z, bb3 = cb[j][3] + bi.w;
            float vA0 = fmaxf(fmaf(pv0, w0, pm0 * bb0), 0.f);
            float vA1 = fmaxf(fmaf(pv0, w1, pm0 * bb1), 0.f);
            float vA2 = fmaxf(fmaf(pv1, w2_, pm1 * bb2), 0.f);
            float vA3 = fmaxf(fmaf(pv1, w3, pm1 * bb3), 0.f);
            float vB0 = fmaxf(fmaf(pv0, bb0, pm0 * w0), 0.f);
            float vB1 = fmaxf(fmaf(pv0, bb1, pm0 * w1), 0.f);
            float vB2 = fmaxf(fmaf(pv1, bb2, pm1 * w2_), 0.f);
            float vB3 = fmaxf(fmaf(pv1, bb3, pm1 * w3), 0.f);
            int ktw = j >> 1;
            int pos = (j & 1) ? 2 : 0;
            split_pack2_fast(vA0, vA1, a0h[ktw][pos],     a0l[ktw][pos]);
            split_pack2_fast(vA2, vA3, a0h[ktw][pos + 1], a0l[ktw][pos + 1]);
            split_pack2_fast(vB0, vB1, a0h[ktw + 2][pos],     a0l[ktw + 2][pos]);
            split_pack2_fast(vB2, vB3, a0h[ktw + 2][pos + 1], a0l[ktw + 2][pos + 1]);
        }

        // ---- layer 0 ----
        float xv[4][4];
        uint32_t a1h[2][4], a1l[2][4];
        #pragma unroll
        for (int n = 0; n < 4; n++) {
            float c0v[4] = {0.f, 0.f, 0.f, 0.f};
            #pragma unroll
            for (int kt = 0; kt < 4; kt++) {
                uint4 Bq = B0u[(n * 4 + kt) * 32 + lane];
                mma16816(c0v, a0h[kt], Bq.x, Bq.y);
                mma16816(c0v, a0l[kt], Bq.x, Bq.y);
                mma16816(c0v, a0h[kt], Bq.z, Bq.w);
            }
            float2 bz = b0f[n * 32 + lane];
            float x0 = fmaxf(c0v[0] + bz.x, 0.f);
            float x1 = fmaxf(c0v[1] + bz.y, 0.f);
            float x2 = fmaxf(c0v[2] + bz.x, 0.f);
            float x3 = fmaxf(c0v[3] + bz.y, 0.f);
            xv[n][0] = x0; xv[n][1] = x1; xv[n][2] = x2; xv[n][3] = x3;
            int ktw = n >> 1;
            int pos = (n & 1) ? 2 : 0;
            split_pack2_fast(x0, x1, a1h[ktw][pos],     a1l[ktw][pos]);
            split_pack2_fast(x2, x3, a1h[ktw][pos + 1], a1l[ktw][pos + 1]);
        }

        // ---- layer 1b + final dot ----
        float rA = 0.f, rB = 0.f;
        #pragma unroll
        for (int n = 0; n < 4; n++) {
            float c1[4] = {0.f, 0.f, 0.f, 0.f};
            #pragma unroll
            for (int kt = 0; kt < 2; kt++) {
                uint4 Bq = B1bu[(n * 2 + kt) * 32 + lane];
                mma16816(c1, a1h[kt], Bq.x, Bq.y);
                mma16816(c1, a1l[kt], Bq.x, Bq.y);
                mma16816(c1, a1h[kt], Bq.z, Bq.w);
            }
            float2 bz = b1f[n * 32 + lane];
            float y0 = fmaxf(c1[0] + bz.x, 0.f);
            float y1 = fmaxf(c1[1] + bz.y, 0.f);
            float y2 = fmaxf(c1[2] + bz.x, 0.f);
            float y3 = fmaxf(c1[3] + bz.y, 0.f);
            float4 w2 = w2f[n * 32 + lane];
            rA = fmaf(w2.x, xv[n][0], rA); rA = fmaf(w2.y, xv[n][1], rA);
            rA = fmaf(w2.z, y0, rA);       rA = fmaf(w2.w, y1, rA);
            rB = fmaf(w2.x, xv[n][2], rB); rB = fmaf(w2.y, xv[n][3], rB);
            rB = fmaf(w2.z, y2, rB);       rB = fmaf(w2.w, y3, rB);
        }
        rA += __shfl_xor_sync(0xFFFFFFFFu, rA, 1);
        rA += __shfl_xor_sync(0xFFFFFFFFu, rA, 2);
        rB += __shfl_xor_sync(0xFFFFFFFFu, rB, 1);
        rB += __shfl_xor_sync(0xFFFFFFFFu, rB, 2);
        if (qp == 0) {
            const float b2v = *((const float*)(packS + OFF_B2));
            long long rowA = pbase + warp * 16 + q;
            long long rowB = rowA + 8;
            if (rowA < (long long)Btot) out[rowA] = rA + b2v;
            if (rowB < (long long)Btot) out[rowB] = rB + b2v;
        }
    }
}

// ======================= launch =======================
extern "C" void kernel_launch(void* const* d_in, const int* in_sizes, int n_in,
                              void* d_out, int out_size) {
    const float* pov   = (const float*)d_in[0];
    const float* white = (const float*)d_in[1];
    const float* black = (const float*)d_in[2];
    const float* Ww = (const float*)d_in[3];
    const float* bw = (const float*)d_in[4];
    const float* Wb = (const float*)d_in[5];
    const float* bb = (const float*)d_in[6];
    const float* W0 = (const float*)d_in[7];
    const float* b0 = (const float*)d_in[8];
    const float* W1 = (const float*)d_in[9];
    const float* b1 = (const float*)d_in[10];
    const float* W2 = (const float*)d_in[11];
    const float* b2 = (const float*)d_in[12];
    const int B = in_sizes[0];

    prep_kernel<<<1, 256>>>(Ww, Wb, W0, W1, bw, bb, b0, b1, W2, b2);

    cudaFuncSetAttribute(nnue_main, cudaFuncAttributeMaxDynamicSharedMemorySize, SMEM_BYTES);
    int grid = (B + ROWS_CTA - 1) / ROWS_CTA;
    nnue_main<<<grid, NT, SMEM_BYTES>>>(pov, white, black, (float*)d_out, B);
}

// round 13
// speedup vs baseline: 3.8355x; 3.8355x over previous
#include <cuda_runtime.h>
#include <cuda_fp16.h>
#include <stdint.h>

// ======================= fragment-packed weight image (fp16 single-digit) =======================
#define OFF_B1    0        // 8*7*32 uint2 = 14336
#define OFF_B0    14336    // 4*4*32 uint2 = 4096
#define OFF_B1B   18432    // 4*2*32 uint2 = 2048
#define OFF_BIAS1 20480    // 2048
#define OFF_B0F   22528    // 1024
#define OFF_B1F   23552    // 1024
#define OFF_W2F   24576    // 2048
#define OFF_B2    26624    // 16
#define PACK_BYTES 26640

__device__ __align__(16) unsigned char g_pack[PACK_BYTES];

// ======================= helpers =======================
__device__ __forceinline__ uint32_t pack_f16x2(float f0, float f1) {
    __half2 h = __floats2half2_rn(f0, f1);     // f0 -> low half
    return *reinterpret_cast<uint32_t*>(&h);
}
// fp16 split: hi = rn(f), lo = rn(f - hi); combined error ~2^-22 (A-side exact)
__device__ __forceinline__ void split_f16_pair(float f0, float f1, uint32_t& hr, uint32_t& lr) {
    __half2 h = __floats2half2_rn(f0, f1);
    hr = *reinterpret_cast<uint32_t*>(&h);
    float g0 = __half2float(__low2half(h));
    float g1 = __half2float(__high2half(h));
    __half2 l = __floats2half2_rn(f0 - g0, f1 - g1);
    lr = *reinterpret_cast<uint32_t*>(&l);
}
__device__ __forceinline__ void mmaf16(float* c, const uint32_t* a, uint32_t b0, uint32_t b1) {
    asm volatile(
        "mma.sync.aligned.m16n8k16.row.col.f32.f16.f16.f32 "
        "{%0,%1,%2,%3}, {%4,%5,%6,%7}, {%8,%9}, {%0,%1,%2,%3};"
        : "+f"(c[0]), "+f"(c[1]), "+f"(c[2]), "+f"(c[3])
        : "r"(a[0]), "r"(a[1]), "r"(a[2]), "r"(a[3]), "r"(b0), "r"(b1));
}

// ======================= prep kernel =======================
__device__ __forceinline__ float getW1c(const float* Ww, const float* Wb, int n, int k) {
    if (k >= 98) return 0.f;
    if (n < 32) return Ww[n * 98 + k];
    int kk = k + 49; if (kk >= 98) kk -= 98;
    return Wb[(n - 32) * 98 + kk];
}

__global__ void prep_kernel(const float* __restrict__ Ww, const float* __restrict__ Wb,
                            const float* __restrict__ W0, const float* __restrict__ W1,
                            const float* __restrict__ bw, const float* __restrict__ bb,
                            const float* __restrict__ b0, const float* __restrict__ b1,
                            const float* __restrict__ W2, const float* __restrict__ b2)
{
    const int tid = threadIdx.x;  // 256 threads
    char* gp = (char*)g_pack;

    // B1 frags: [nt 0..7][kt 0..6][lane] uint2 {pair(k0,k0+1), pair(k0+8,k0+9)}
    for (int idx = tid; idx < 8 * 7 * 32; idx += 256) {
        int lane = idx & 31, t = idx >> 5;
        int kt = t % 7, nt = t / 7;
        int n = nt * 8 + (lane >> 2);
        int k0 = kt * 16 + (lane & 3) * 2;
        uint2 v;
        v.x = pack_f16x2(getW1c(Ww, Wb, n, k0),     getW1c(Ww, Wb, n, k0 + 1));
        v.y = pack_f16x2(getW1c(Ww, Wb, n, k0 + 8), getW1c(Ww, Wb, n, k0 + 9));
        ((uint2*)(gp + OFF_B1))[idx] = v;
    }
    // B0 frags: [nt 0..3][kt 0..3][lane]
    for (int idx = tid; idx < 4 * 4 * 32; idx += 256) {
        int lane = idx & 31, t = idx >> 5;
        int kt = t & 3, nt = t >> 2;
        int n = nt * 8 + (lane >> 2);
        int k0 = kt * 16 + (lane & 3) * 2;
        uint2 v;
        v.x = pack_f16x2(W0[n * 64 + k0],     W0[n * 64 + k0 + 1]);
        v.y = pack_f16x2(W0[n * 64 + k0 + 8], W0[n * 64 + k0 + 9]);
        ((uint2*)(gp + OFF_B0))[idx] = v;
    }
    // B1b frags: [nt 0..3][kt 0..1][lane]
    for (int idx = tid; idx < 4 * 2 * 32; idx += 256) {
        int lane = idx & 31, t = idx >> 5;
        int kt = t & 1, nt = t >> 1;
        int n = nt * 8 + (lane >> 2);
        int k0 = kt * 16 + (lane & 3) * 2;
        uint2 v;
        v.x = pack_f16x2(W1[n * 32 + k0],     W1[n * 32 + k0 + 1]);
        v.y = pack_f16x2(W1[n * 32 + k0 + 8], W1[n * 32 + k0 + 9]);
        ((uint2*)(gp + OFF_B1B))[idx] = v;
    }
    // bias / W2 frags (fp32, unchanged layout)
    for (int idx = tid; idx < 4 * 32; idx += 256) {
        int lane = idx & 31, j = idx >> 5;
        int c = j * 8 + (lane & 3) * 2;
        float4 bf; bf.x = bw[c]; bf.y = bw[c + 1]; bf.z = bb[c]; bf.w = bb[c + 1];
        ((float4*)(gp + OFF_BIAS1))[idx] = bf;
        float2 f0; f0.x = b0[c]; f0.y = b0[c + 1];
        ((float2*)(gp + OFF_B0F))[idx] = f0;
        float2 f1; f1.x = b1[c]; f1.y = b1[c + 1];
        ((float2*)(gp + OFF_B1F))[idx] = f1;
        float4 w2; w2.x = W2[c]; w2.y = W2[c + 1]; w2.z = W2[32 + c]; w2.w = W2[32 + c + 1];
        ((float4*)(gp + OFF_W2F))[idx] = w2;
    }
    if (tid == 0) *((float*)(gp + OFF_B2)) = b2[0];
}

// ======================= main fused kernel (R8 chassis) =======================
// 256 threads (8 warps), 256 rows per CTA, 2 passes of 128 staged f32 rows.
// smem: [pack 26640][st 128*104 f32 = 53248][spov 1024] = 80928 B -> 2 CTAs/SM
#define NT 256
#define ROWS_CTA 256
#define STAGE_ROWS 128
#define ST_STRIDE 104
#define SMEM_BYTES (PACK_BYTES + STAGE_ROWS * ST_STRIDE * 4 + ROWS_CTA * 4 + 16)

__global__ void __launch_bounds__(NT, 2)
nnue_main(const float* __restrict__ pov, const float* __restrict__ white,
          const float* __restrict__ black, float* __restrict__ out, int Btot)
{
    extern __shared__ __align__(16) unsigned char smem[];
    unsigned char* packS = smem;
    float* st   = (float*)(smem + PACK_BYTES);
    float* spov = st + STAGE_ROWS * ST_STRIDE;

    const int tid  = threadIdx.x;
    const int warp = tid >> 5;
    const int lane = tid & 31;
    const int q    = lane >> 2;
    const int qp   = lane & 3;
    const long long cbase = (long long)blockIdx.x * ROWS_CTA;

    // ---- copy weight pack into smem (once) ----
    {
        const uint4* src = (const uint4*)g_pack;
        uint4* dst = (uint4*)packS;
        #pragma unroll 4
        for (int i = tid; i < PACK_BYTES / 16; i += NT) dst[i] = src[i];
    }
    spov[tid] = (cbase + tid < (long long)Btot) ? __ldcs(pov + cbase + tid) : 0.f;

    const uint2*  B1u  = (const uint2*)(packS + OFF_B1);
    const uint2*  B0u  = (const uint2*)(packS + OFF_B0);
    const uint2*  B1bu = (const uint2*)(packS + OFF_B1B);
    const float4* bia1 = (const float4*)(packS + OFF_BIAS1);
    const float2* b0f  = (const float2*)(packS + OFF_B0F);
    const float2* b1f  = (const float2*)(packS + OFF_B1F);
    const float4* w2f  = (const float4*)(packS + OFF_W2F);

    #pragma unroll 1
    for (int pass = 0; pass < 2; pass++) {
        const long long pbase = cbase + pass * STAGE_ROWS;
        if (pass > 0) __syncthreads();

        // ---- zero pad cols 98..103 (128 staged rows) ----
        if (tid < STAGE_ROWS) {
            #pragma unroll
            for (int c = 98; c < 104; c++) st[tid * ST_STRIDE + c] = 0.f;
        }

        // ---- stage 128 rows (coalesced float4, streaming) ----
        if (pbase + STAGE_ROWS <= (long long)Btot) {
            const float4* gw = (const float4*)(white + pbase * 49);
            const float4* gb = (const float4*)(black + pbase * 49);
            #pragma unroll 2
            for (int i = tid; i < 1568; i += NT) {   // 128*49/4
                float4 v = __ldcs(gw + i);
                int g = 4 * i;
                #pragma unroll
                for (int e = 0; e < 4; e++) {
                    int gg = g + e;
                    int s = gg / 49, c = gg - s * 49;
                    float val = (e == 0) ? v.x : (e == 1) ? v.y : (e == 2) ? v.z : v.w;
                    st[s * ST_STRIDE + c] = val;
                }
                float4 u = __ldcs(gb + i);
                #pragma unroll
                for (int e = 0; e < 4; e++) {
                    int gg = g + e;
                    int s = gg / 49, c = gg - s * 49;
                    float val = (e == 0) ? u.x : (e == 1) ? u.y : (e == 2) ? u.z : u.w;
                    st[s * ST_STRIDE + 49 + c] = val;
                }
            }
        } else {
            for (int i = tid; i < STAGE_ROWS * 49; i += NT) {
                int s = i / 49, c = i - s * 49;
                long long row = pbase + s;
                bool ok = row < (long long)Btot;
                st[s * ST_STRIDE + c]      = ok ? white[row * 49 + c] : 0.f;
                st[s * ST_STRIDE + 49 + c] = ok ? black[row * 49 + c] : 0.f;
            }
        }
        __syncthreads();

        // ---- this warp's m16 tile: local rows warp*16 + q, + 8 ----
        const float* r0 = st + (warp * 16 + q) * ST_STRIDE;
        const float* r1 = r0 + 8 * ST_STRIDE;

        // ================= layer 1 (2-pass fp16) =================
        float cw[4][4], cb[4][4];
        #pragma unroll
        for (int j = 0; j < 4; j++)
            #pragma unroll
            for (int i = 0; i < 4; i++) { cw[j][i] = 0.f; cb[j][i] = 0.f; }

        #pragma unroll
        for (int kt = 0; kt < 7; kt++) {
            const int c0 = kt * 16 + qp * 2;
            uint32_t ah[4], al[4];
            float2 p;
            p = *(const float2*)(r0 + c0); split_f16_pair(p.x, p.y, ah[0], al[0]);
            p = *(const float2*)(r1 + c0); split_f16_pair(p.x, p.y, ah[1], al[1]);
            if (kt < 6) {
                p = *(const float2*)(r0 + c0 + 8); split_f16_pair(p.x, p.y, ah[2], al[2]);
                p = *(const float2*)(r1 + c0 + 8); split_f16_pair(p.x, p.y, ah[3], al[3]);
            } else {
                ah[2] = al[2] = ah[3] = al[3] = 0u;
            }
            #pragma unroll
            for (int j = 0; j < 4; j++) {
                uint2 Bw = B1u[(j * 7 + kt) * 32 + lane];
                uint2 Bb = B1u[((j + 4) * 7 + kt) * 32 + lane];
                mmaf16(cw[j], ah, Bw.x, Bw.y);
                mmaf16(cw[j], al, Bw.x, Bw.y);
                mmaf16(cb[j], ah, Bb.x, Bb.y);
                mmaf16(cb[j], al, Bb.x, Bb.y);
            }
        }

        // ---- epilogue 1: bias + pov mix + relu -> layer-0 A frags ----
        const int prow = pass * STAGE_ROWS + warp * 16 + q;
        float pv0 = spov[prow];
        float pv1 = spov[prow + 8];
        float pm0 = 1.f - pv0, pm1 = 1.f - pv1;

        uint32_t a0h[4][4], a0l[4][4];
        #pragma unroll
        for (int j = 0; j < 4; j++) {
            float4 bi = bia1[j * 32 + lane];
            float w0 = cw[j][0] + bi.x, w1 = cw[j][1] + bi.y;
            float w2_ = cw[j][2] + bi.x, w3 = cw[j][3] + bi.y;
            float bb0 = cb[j][0] + bi.z, bb1 = cb[j][1] + bi.w;
            float bb2 = cb[j][2] + bi.z, bb3 = cb[j][3] + bi.w;
            float vA0 = fmaxf(fmaf(pv0, w0, pm0 * bb0), 0.f);
            float vA1 = fmaxf(fmaf(pv0, w1, pm0 * bb1), 0.f);
            float vA2 = fmaxf(fmaf(pv1, w2_, pm1 * bb2), 0.f);
            float vA3 = fmaxf(fmaf(pv1, w3, pm1 * bb3), 0.f);
            float vB0 = fmaxf(fmaf(pv0, bb0, pm0 * w0), 0.f);
            float vB1 = fmaxf(fmaf(pv0, bb1, pm0 * w1), 0.f);
            float vB2 = fmaxf(fmaf(pv1, bb2, pm1 * w2_), 0.f);
            float vB3 = fmaxf(fmaf(pv1, bb3, pm1 * w3), 0.f);
            int ktw = j >> 1;
            int pos = (j & 1) ? 2 : 0;
            split_f16_pair(vA0, vA1, a0h[ktw][pos],     a0l[ktw][pos]);
            split_f16_pair(vA2, vA3, a0h[ktw][pos + 1], a0l[ktw][pos + 1]);
            split_f16_pair(vB0, vB1, a0h[ktw + 2][pos],     a0l[ktw + 2][pos]);
            split_f16_pair(vB2, vB3, a0h[ktw + 2][pos + 1], a0l[ktw + 2][pos + 1]);
        }

        // ---- layer 0 (2-pass fp16) ----
        float xv[4][4];
        uint32_t a1h[2][4], a1l[2][4];
        #pragma unroll
        for (int n = 0; n < 4; n++) {
            float c0v[4] = {0.f, 0.f, 0.f, 0.f};
            #pragma unroll
            for (int kt = 0; kt < 4; kt++) {
                uint2 Bq = B0u[(n * 4 + kt) * 32 + lane];
                mmaf16(c0v, a0h[kt], Bq.x, Bq.y);
                mmaf16(c0v, a0l[kt], Bq.x, Bq.y);
            }
            float2 bz = b0f[n * 32 + lane];
            float x0 = fmaxf(c0v[0] + bz.x, 0.f);
            float x1 = fmaxf(c0v[1] + bz.y, 0.f);
            float x2 = fmaxf(c0v[2] + bz.x, 0.f);
            float x3 = fmaxf(c0v[3] + bz.y, 0.f);
            xv[n][0] = x0; xv[n][1] = x1; xv[n][2] = x2; xv[n][3] = x3;
            int ktw = n >> 1;
            int pos = (n & 1) ? 2 : 0;
            split_f16_pair(x0, x1, a1h[ktw][pos],     a1l[ktw][pos]);
            split_f16_pair(x2, x3, a1h[ktw][pos + 1], a1l[ktw][pos + 1]);
        }

        // ---- layer 1b (2-pass fp16) + final dot ----
        float rA = 0.f, rB = 0.f;
        #pragma unroll
        for (int n = 0; n < 4; n++) {
            float c1[4] = {0.f, 0.f, 0.f, 0.f};
            #pragma unroll
            for (int kt = 0; kt < 2; kt++) {
                uint2 Bq = B1bu[(n * 2 + kt) * 32 + lane];
                mmaf16(c1, a1h[kt], Bq.x, Bq.y);
                mmaf16(c1, a1l[kt], Bq.x, Bq.y);
            }
            float2 bz = b1f[n * 32 + lane];
            float y0 = fmaxf(c1[0] + bz.x, 0.f);
            float y1 = fmaxf(c1[1] + bz.y, 0.f);
            float y2 = fmaxf(c1[2] + bz.x, 0.f);
            float y3 = fmaxf(c1[3] + bz.y, 0.f);
            float4 w2 = w2f[n * 32 + lane];
            rA = fmaf(w2.x, xv[n][0], rA); rA = fmaf(w2.y, xv[n][1], rA);
            rA = fmaf(w2.z, y0, rA);       rA = fmaf(w2.w, y1, rA);
            rB = fmaf(w2.x, xv[n][2], rB); rB = fmaf(w2.y, xv[n][3], rB);
            rB = fmaf(w2.z, y2, rB);       rB = fmaf(w2.w, y3, rB);
        }
        rA += __shfl_xor_sync(0xFFFFFFFFu, rA, 1);
        rA += __shfl_xor_sync(0xFFFFFFFFu, rA, 2);
        rB += __shfl_xor_sync(0xFFFFFFFFu, rB, 1);
        rB += __shfl_xor_sync(0xFFFFFFFFu, rB, 2);
        if (qp == 0) {
            const float b2v = *((const float*)(packS + OFF_B2));
            long long rowA = pbase + warp * 16 + q;
            long long rowB = rowA + 8;
            if (rowA < (long long)Btot) out[rowA] = rA + b2v;
            if (rowB < (long long)Btot) out[rowB] = rB + b2v;
        }
    }
}

// ======================= launch =======================
extern "C" void kernel_launch(void* const* d_in, const int* in_sizes, int n_in,
                              void* d_out, int out_size) {
    const float* pov   = (const float*)d_in[0];
    const float* white = (const float*)d_in[1];
    const float* black = (const float*)d_in[2];
    const float* Ww = (const float*)d_in[3];
    const float* bw = (const float*)d_in[4];
    const float* Wb = (const float*)d_in[5];
    const float* bb = (const float*)d_in[6];
    const float* W0 = (const float*)d_in[7];
    const float* b0 = (const float*)d_in[8];
    const float* W1 = (const float*)d_in[9];
    const float* b1 = (const float*)d_in[10];
    const float* W2 = (const float*)d_in[11];
    const float* b2 = (const float*)d_in[12];
    const int B = in_sizes[0];

    prep_kernel<<<1, 256>>>(Ww, Wb, W0, W1, bw, bb, b0, b1, W2, b2);

    cudaFuncSetAttribute(nnue_main, cudaFuncAttributeMaxDynamicSharedMemorySize, SMEM_BYTES);
    int grid = (B + ROWS_CTA - 1) / ROWS_CTA;
    nnue_main<<<grid, NT, SMEM_BYTES>>>(pov, white, black, (float*)d_out, B);
}

// round 14
// speedup vs baseline: 4.1381x; 1.0789x over previous
#include <cuda_runtime.h>
#include <cuda_fp16.h>
#include <stdint.h>

// ======================= fragment-packed weight image =======================
#define OFF_B1    0        // 4*7*32 uint4 = 14336  {Ww p0, Ww p8, Wb p0, Wb p8}
#define OFF_B0    14336    // 4*4*32 uint2 = 4096
#define OFF_B1B   18432    // 4*2*32 uint2 = 2048
#define OFF_BIAS1 20480    // 2048
#define OFF_B0F   22528    // 1024
#define OFF_B1F   23552    // 1024
#define OFF_W2F   24576    // 2048
#define OFF_B2    26624    // 16
#define PACK_BYTES 26640

__device__ __align__(16) unsigned char g_pack[PACK_BYTES];

// ======================= helpers =======================
__device__ __forceinline__ uint32_t pack_f16x2(float f0, float f1) {
    __half2 h = __floats2half2_rn(f0, f1);     // f0 -> low half
    return *reinterpret_cast<uint32_t*>(&h);
}
// fp16 split: hi = rn(f), lo = rn(f - hi)
__device__ __forceinline__ void split_f16_pair(float f0, float f1, uint32_t& hr, uint32_t& lr) {
    __half2 h = __floats2half2_rn(f0, f1);
    hr = *reinterpret_cast<uint32_t*>(&h);
    float g0 = __half2float(__low2half(h));
    float g1 = __half2float(__high2half(h));
    __half2 l = __floats2half2_rn(f0 - g0, f1 - g1);
    lr = *reinterpret_cast<uint32_t*>(&l);
}
__device__ __forceinline__ void mmaf16(float* c, const uint32_t* a, uint32_t b0, uint32_t b1) {
    asm volatile(
        "mma.sync.aligned.m16n8k16.row.col.f32.f16.f16.f32 "
        "{%0,%1,%2,%3}, {%4,%5,%6,%7}, {%8,%9}, {%0,%1,%2,%3};"
        : "+f"(c[0]), "+f"(c[1]), "+f"(c[2]), "+f"(c[3])
        : "r"(a[0]), "r"(a[1]), "r"(a[2]), "r"(a[3]), "r"(b0), "r"(b1));
}

// ======================= prep kernel =======================
__device__ __forceinline__ float getW1c(const float* Ww, const float* Wb, int n, int k) {
    if (k >= 98) return 0.f;
    if (n < 32) return Ww[n * 98 + k];
    int kk = k + 49; if (kk >= 98) kk -= 98;
    return Wb[(n - 32) * 98 + kk];
}

__global__ void prep_kernel(const float* __restrict__ Ww, const float* __restrict__ Wb,
                            const float* __restrict__ W0, const float* __restrict__ W1,
                            const float* __restrict__ bw, const float* __restrict__ bb,
                            const float* __restrict__ b0, const float* __restrict__ b1,
                            const float* __restrict__ W2, const float* __restrict__ b2)
{
    const int tid = threadIdx.x;  // 256 threads
    char* gp = (char*)g_pack;

    // B1 frags: [j 0..3][kt 0..6][lane] uint4 {Ww(k0,k0+1), Ww(k0+8,k0+9), Wb(...), Wb(...)}
    for (int idx = tid; idx < 4 * 7 * 32; idx += 256) {
        int lane = idx & 31, t = idx >> 5;
        int kt = t % 7, j = t / 7;
        int nw = j * 8 + (lane >> 2);          // Ww combined row (n < 32)
        int nb = nw + 32;                      // Wb combined row
        int k0 = kt * 16 + (lane & 3) * 2;
        uint4 v;
        v.x = pack_f16x2(getW1c(Ww, Wb, nw, k0),     getW1c(Ww, Wb, nw, k0 + 1));
        v.y = pack_f16x2(getW1c(Ww, Wb, nw, k0 + 8), getW1c(Ww, Wb, nw, k0 + 9));
        v.z = pack_f16x2(getW1c(Ww, Wb, nb, k0),     getW1c(Ww, Wb, nb, k0 + 1));
        v.w = pack_f16x2(getW1c(Ww, Wb, nb, k0 + 8), getW1c(Ww, Wb, nb, k0 + 9));
        ((uint4*)(gp + OFF_B1))[idx] = v;
    }
    // B0 frags: [nt 0..3][kt 0..3][lane]
    for (int idx = tid; idx < 4 * 4 * 32; idx += 256) {
        int lane = idx & 31, t = idx >> 5;
        int kt = t & 3, nt = t >> 2;
        int n = nt * 8 + (lane >> 2);
        int k0 = kt * 16 + (lane & 3) * 2;
        uint2 v;
        v.x = pack_f16x2(W0[n * 64 + k0],     W0[n * 64 + k0 + 1]);
        v.y = pack_f16x2(W0[n * 64 + k0 + 8], W0[n * 64 + k0 + 9]);
        ((uint2*)(gp + OFF_B0))[idx] = v;
    }
    // B1b frags: [nt 0..3][kt 0..1][lane]
    for (int idx = tid; idx < 4 * 2 * 32; idx += 256) {
        int lane = idx & 31, t = idx >> 5;
        int kt = t & 1, nt = t >> 1;
        int n = nt * 8 + (lane >> 2);
        int k0 = kt * 16 + (lane & 3) * 2;
        uint2 v;
        v.x = pack_f16x2(W1[n * 32 + k0],     W1[n * 32 + k0 + 1]);
        v.y = pack_f16x2(W1[n * 32 + k0 + 8], W1[n * 32 + k0 + 9]);
        ((uint2*)(gp + OFF_B1B))[idx] = v;
    }
    // bias / W2 frags (fp32)
    for (int idx = tid; idx < 4 * 32; idx += 256) {
        int lane = idx & 31, j = idx >> 5;
        int c = j * 8 + (lane & 3) * 2;
        float4 bf; bf.x = bw[c]; bf.y = bw[c + 1]; bf.z = bb[c]; bf.w = bb[c + 1];
        ((float4*)(gp + OFF_BIAS1))[idx] = bf;
        float2 f0; f0.x = b0[c]; f0.y = b0[c + 1];
        ((float2*)(gp + OFF_B0F))[idx] = f0;
        float2 f1; f1.x = b1[c]; f1.y = b1[c + 1];
        ((float2*)(gp + OFF_B1F))[idx] = f1;
        float4 w2; w2.x = W2[c]; w2.y = W2[c + 1]; w2.z = W2[32 + c]; w2.w = W2[32 + c + 1];
        ((float4*)(gp + OFF_W2F))[idx] = w2;
    }
    if (tid == 0) *((float*)(gp + OFF_B2)) = b2[0];
}

// ======================= main fused kernel =======================
// 192 threads (6 warps), 192 rows/CTA, 2 passes of 96 staged f32 rows.
// smem: [pack 26640][st 96*104*4 = 39936][spov 768] = 67360 B -> 3 CTAs/SM (18 warps)
#define NT 192
#define ROWS_CTA 192
#define STAGE_ROWS 96
#define ST_STRIDE 104
#define SMEM_BYTES (PACK_BYTES + STAGE_ROWS * ST_STRIDE * 4 + ROWS_CTA * 4 + 16)

__global__ void __launch_bounds__(NT, 3)
nnue_main(const float* __restrict__ pov, const float* __restrict__ white,
          const float* __restrict__ black, float* __restrict__ out, int Btot)
{
    extern __shared__ __align__(16) unsigned char smem[];
    unsigned char* packS = smem;
    float* st   = (float*)(smem + PACK_BYTES);
    float* spov = st + STAGE_ROWS * ST_STRIDE;

    const int tid  = threadIdx.x;
    const int warp = tid >> 5;
    const int lane = tid & 31;
    const int q    = lane >> 2;
    const int qp   = lane & 3;
    const long long cbase = (long long)blockIdx.x * ROWS_CTA;

    // ---- copy weight pack into smem (once) ----
    {
        const uint4* src = (const uint4*)g_pack;
        uint4* dst = (uint4*)packS;
        #pragma unroll 4
        for (int i = tid; i < PACK_BYTES / 16; i += NT) dst[i] = src[i];
    }
    spov[tid] = (cbase + tid < (long long)Btot) ? __ldcs(pov + cbase + tid) : 0.f;

    const uint4*  B1u  = (const uint4*)(packS + OFF_B1);
    const uint2*  B0u  = (const uint2*)(packS + OFF_B0);
    const uint2*  B1bu = (const uint2*)(packS + OFF_B1B);
    const float4* bia1 = (const float4*)(packS + OFF_BIAS1);
    const float2* b0f  = (const float2*)(packS + OFF_B0F);
    const float2* b1f  = (const float2*)(packS + OFF_B1F);
    const float4* w2f  = (const float4*)(packS + OFF_W2F);

    #pragma unroll 1
    for (int pass = 0; pass < 2; pass++) {
        const long long pbase = cbase + pass * STAGE_ROWS;
        if (pass > 0) __syncthreads();

        // ---- zero pad cols 98..103 ----
        if (tid < STAGE_ROWS) {
            #pragma unroll
            for (int c = 98; c < 104; c++) st[tid * ST_STRIDE + c] = 0.f;
        }

        // ---- stage 96 rows (coalesced float4, streaming) ----
        if (pbase + STAGE_ROWS <= (long long)Btot) {
            const float4* gw = (const float4*)(white + pbase * 49);
            const float4* gb = (const float4*)(black + pbase * 49);
            #pragma unroll 2
            for (int i = tid; i < 1176; i += NT) {   // 96*49/4
                float4 v = __ldcs(gw + i);
                int g = 4 * i;
                #pragma unroll
                for (int e = 0; e < 4; e++) {
                    int gg = g + e;
                    int s = gg / 49, c = gg - s * 49;
                    float val = (e == 0) ? v.x : (e == 1) ? v.y : (e == 2) ? v.z : v.w;
                    st[s * ST_STRIDE + c] = val;
                }
                float4 u = __ldcs(gb + i);
                #pragma unroll
                for (int e = 0; e < 4; e++) {
                    int gg = g + e;
                    int s = gg / 49, c = gg - s * 49;
                    float val = (e == 0) ? u.x : (e == 1) ? u.y : (e == 2) ? u.z : u.w;
                    st[s * ST_STRIDE + 49 + c] = val;
                }
            }
        } else {
            for (int i = tid; i < STAGE_ROWS * 49; i += NT) {
                int s = i / 49, c = i - s * 49;
                long long row = pbase + s;
                bool ok = row < (long long)Btot;
                st[s * ST_STRIDE + c]      = ok ? white[row * 49 + c] : 0.f;
                st[s * ST_STRIDE + 49 + c] = ok ? black[row * 49 + c] : 0.f;
            }
        }
        __syncthreads();

        // ---- this warp's m16 tile: local rows warp*16 + q, + 8 ----
        const float* r0 = st + (warp * 16 + q) * ST_STRIDE;
        const float* r1 = r0 + 8 * ST_STRIDE;

        // ================= layer 1: single-digit fp16 A (1 pass) =================
        float cw[4][4], cb[4][4];
        #pragma unroll
        for (int j = 0; j < 4; j++)
            #pragma unroll
            for (int i = 0; i < 4; i++) { cw[j][i] = 0.f; cb[j][i] = 0.f; }

        #pragma unroll
        for (int kt = 0; kt < 7; kt++) {
            const int c0 = kt * 16 + qp * 2;
            uint32_t ah[4];
            float2 p;
            p = *(const float2*)(r0 + c0); ah[0] = pack_f16x2(p.x, p.y);
            p = *(const float2*)(r1 + c0); ah[1] = pack_f16x2(p.x, p.y);
            if (kt < 6) {
                p = *(const float2*)(r0 + c0 + 8); ah[2] = pack_f16x2(p.x, p.y);
                p = *(const float2*)(r1 + c0 + 8); ah[3] = pack_f16x2(p.x, p.y);
            } else {
                ah[2] = ah[3] = 0u;
            }
            #pragma unroll
            for (int j = 0; j < 4; j++) {
                uint4 Bq = B1u[(j * 7 + kt) * 32 + lane];
                mmaf16(cw[j], ah, Bq.x, Bq.y);
                mmaf16(cb[j], ah, Bq.z, Bq.w);
            }
        }

        // ---- epilogue 1: bias + pov mix + relu -> layer-0 A frags (2-digit) ----
        const int prow = pass * STAGE_ROWS + warp * 16 + q;
        float pv0 = spov[prow];
        float pv1 = spov[prow + 8];
        float pm0 = 1.f - pv0, pm1 = 1.f - pv1;

        uint32_t a0h[4][4], a0l[4][4];
        #pragma unroll
        for (int j = 0; j < 4; j++) {
            float4 bi = bia1[j * 32 + lane];
            float w0 = cw[j][0] + bi.x, w1 = cw[j][1] + bi.y;
            float w2_ = cw[j][2] + bi.x, w3 = cw[j][3] + bi.y;
            float bb0 = cb[j][0] + bi.z, bb1 = cb[j][1] + bi.w;
            float bb2 = cb[j][2] + bi.z, bb3 = cb[j][3] + bi.w;
            float vA0 = fmaxf(fmaf(pv0, w0, pm0 * bb0), 0.f);
            float vA1 = fmaxf(fmaf(pv0, w1, pm0 * bb1), 0.f);
            float vA2 = fmaxf(fmaf(pv1, w2_, pm1 * bb2), 0.f);
            float vA3 = fmaxf(fmaf(pv1, w3, pm1 * bb3), 0.f);
            float vB0 = fmaxf(fmaf(pv0, bb0, pm0 * w0), 0.f);
            float vB1 = fmaxf(fmaf(pv0, bb1, pm0 * w1), 0.f);
            float vB2 = fmaxf(fmaf(pv1, bb2, pm1 * w2_), 0.f);
            float vB3 = fmaxf(fmaf(pv1, bb3, pm1 * w3), 0.f);
            int ktw = j >> 1;
            int pos = (j & 1) ? 2 : 0;
            split_f16_pair(vA0, vA1, a0h[ktw][pos],     a0l[ktw][pos]);
            split_f16_pair(vA2, vA3, a0h[ktw][pos + 1], a0l[ktw][pos + 1]);
            split_f16_pair(vB0, vB1, a0h[ktw + 2][pos],     a0l[ktw + 2][pos]);
            split_f16_pair(vB2, vB3, a0h[ktw + 2][pos + 1], a0l[ktw + 2][pos + 1]);
        }

        // ---- layer 0 (2-pass fp16) ----
        float xv[4][4];
        uint32_t a1h[2][4], a1l[2][4];
        #pragma unroll
        for (int n = 0; n < 4; n++) {
            float c0v[4] = {0.f, 0.f, 0.f, 0.f};
            #pragma unroll
            for (int kt = 0; kt < 4; kt++) {
                uint2 Bq = B0u[(n * 4 + kt) * 32 + lane];
                mmaf16(c0v, a0h[kt], Bq.x, Bq.y);
                mmaf16(c0v, a0l[kt], Bq.x, Bq.y);
            }
            float2 bz = b0f[n * 32 + lane];
            float x0 = fmaxf(c0v[0] + bz.x, 0.f);
            float x1 = fmaxf(c0v[1] + bz.y, 0.f);
            float x2 = fmaxf(c0v[2] + bz.x, 0.f);
            float x3 = fmaxf(c0v[3] + bz.y, 0.f);
            xv[n][0] = x0; xv[n][1] = x1; xv[n][2] = x2; xv[n][3] = x3;
            int ktw = n >> 1;
            int pos = (n & 1) ? 2 : 0;
            split_f16_pair(x0, x1, a1h[ktw][pos],     a1l[ktw][pos]);
            split_f16_pair(x2, x3, a1h[ktw][pos + 1], a1l[ktw][pos + 1]);
        }

        // ---- layer 1b (2-pass fp16) + final dot ----
        float rA = 0.f, rB = 0.f;
        #pragma unroll
        for (int n = 0; n < 4; n++) {
            float c1[4] = {0.f, 0.f, 0.f, 0.f};
            #pragma unroll
            for (int kt = 0; kt < 2; kt++) {
                uint2 Bq = B1bu[(n * 2 + kt) * 32 + lane];
                mmaf16(c1, a1h[kt], Bq.x, Bq.y);
                mmaf16(c1, a1l[kt], Bq.x, Bq.y);
            }
            float2 bz = b1f[n * 32 + lane];
            float y0 = fmaxf(c1[0] + bz.x, 0.f);
            float y1 = fmaxf(c1[1] + bz.y, 0.f);
            float y2 = fmaxf(c1[2] + bz.x, 0.f);
            float y3 = fmaxf(c1[3] + bz.y, 0.f);
            float4 w2 = w2f[n * 32 + lane];
            rA = fmaf(w2.x, xv[n][0], rA); rA = fmaf(w2.y, xv[n][1], rA);
            rA = fmaf(w2.z, y0, rA);       rA = fmaf(w2.w, y1, rA);
            rB = fmaf(w2.x, xv[n][2], rB); rB = fmaf(w2.y, xv[n][3], rB);
            rB = fmaf(w2.z, y2, rB);       rB = fmaf(w2.w, y3, rB);
        }
        rA += __shfl_xor_sync(0xFFFFFFFFu, rA, 1);
        rA += __shfl_xor_sync(0xFFFFFFFFu, rA, 2);
        rB += __shfl_xor_sync(0xFFFFFFFFu, rB, 1);
        rB += __shfl_xor_sync(0xFFFFFFFFu, rB, 2);
        if (qp == 0) {
            const float b2v = *((const float*)(packS + OFF_B2));
            long long rowA = pbase + warp * 16 + q;
            long long rowB = rowA + 8;
            if (rowA < (long long)Btot) out[rowA] = rA + b2v;
            if (rowB < (long long)Btot) out[rowB] = rB + b2v;
        }
    }
}

// ======================= launch =======================
extern "C" void kernel_launch(void* const* d_in, const int* in_sizes, int n_in,
                              void* d_out, int out_size) {
    const float* pov   = (const float*)d_in[0];
    const float* white = (const float*)d_in[1];
    const float* black = (const float*)d_in[2];
    const float* Ww = (const float*)d_in[3];
    const float* bw = (const float*)d_in[4];
    const float* Wb = (const float*)d_in[5];
    const float* bb = (const float*)d_in[6];
    const float* W0 = (const float*)d_in[7];
    const float* b0 = (const float*)d_in[8];
    const float* W1 = (const float*)d_in[9];
    const float* b1 = (const float*)d_in[10];
    const float* W2 = (const float*)d_in[11];
    const float* b2 = (const float*)d_in[12];
    const int B = in_sizes[0];

    prep_kernel<<<1, 256>>>(Ww, Wb, W0, W1, bw, bb, b0, b1, W2, b2);

    cudaFuncSetAttribute(nnue_main, cudaFuncAttributeMaxDynamicSharedMemorySize, SMEM_BYTES);
    int grid = (B + ROWS_CTA - 1) / ROWS_CTA;
    nnue_main<<<grid, NT, SMEM_BYTES>>>(pov, white, black, (float*)d_out, B);
}

// round 16
// speedup vs baseline: 4.3879x; 1.0604x over previous
#include <cuda_runtime.h>
#include <cuda_fp16.h>
#include <stdint.h>

// ======================= fragment-packed weight image =======================
#define OFF_B1    0        // 4*7*32 uint4 = 14336  {Ww p0, Ww p8, Wb p0, Wb p8}
#define OFF_B0    14336    // 4*4*32 uint2 = 4096
#define OFF_B1B   18432    // 4*2*32 uint2 = 2048
#define OFF_BIAS1 20480    // 2048
#define OFF_B0F   22528    // 1024
#define OFF_B1F   23552    // 1024
#define OFF_W2F   24576    // 2048
#define OFF_B2    26624    // 16
#define PACK_BYTES 26640

__device__ __align__(16) unsigned char g_pack[PACK_BYTES];

// ======================= helpers =======================
__device__ __forceinline__ uint32_t pack_f16x2(float f0, float f1) {
    __half2 h = __floats2half2_rn(f0, f1);     // f0 -> low half
    return *reinterpret_cast<uint32_t*>(&h);
}
// fp16 split: hi = rn(f), lo = rn(f - hi)
__device__ __forceinline__ void split_f16_pair(float f0, float f1, uint32_t& hr, uint32_t& lr) {
    __half2 h = __floats2half2_rn(f0, f1);
    hr = *reinterpret_cast<uint32_t*>(&h);
    float g0 = __half2float(__low2half(h));
    float g1 = __half2float(__high2half(h));
    __half2 l = __floats2half2_rn(f0 - g0, f1 - g1);
    lr = *reinterpret_cast<uint32_t*>(&l);
}
__device__ __forceinline__ void mmaf16(float* c, const uint32_t* a, uint32_t b0, uint32_t b1) {
    asm volatile(
        "mma.sync.aligned.m16n8k16.row.col.f32.f16.f16.f32 "
        "{%0,%1,%2,%3}, {%4,%5,%6,%7}, {%8,%9}, {%0,%1,%2,%3};"
        : "+f"(c[0]), "+f"(c[1]), "+f"(c[2]), "+f"(c[3])
        : "r"(a[0]), "r"(a[1]), "r"(a[2]), "r"(a[3]), "r"(b0), "r"(b1));
}

// ======================= prep kernel (unchanged from R14) =======================
__device__ __forceinline__ float getW1c(const float* Ww, const float* Wb, int n, int k) {
    if (k >= 98) return 0.f;
    if (n < 32) return Ww[n * 98 + k];
    int kk = k + 49; if (kk >= 98) kk -= 98;
    return Wb[(n - 32) * 98 + kk];
}

__global__ void prep_kernel(const float* __restrict__ Ww, const float* __restrict__ Wb,
                            const float* __restrict__ W0, const float* __restrict__ W1,
                            const float* __restrict__ bw, const float* __restrict__ bb,
                            const float* __restrict__ b0, const float* __restrict__ b1,
                            const float* __restrict__ W2, const float* __restrict__ b2)
{
    const int tid = threadIdx.x;  // 256 threads
    char* gp = (char*)g_pack;

    // B1 frags: [j 0..3][kt 0..6][lane] uint4 {Ww(k0,k0+1), Ww(k0+8,k0+9), Wb(...), Wb(...)}
    for (int idx = tid; idx < 4 * 7 * 32; idx += 256) {
        int lane = idx & 31, t = idx >> 5;
        int kt = t % 7, j = t / 7;
        int nw = j * 8 + (lane >> 2);
        int nb = nw + 32;
        int k0 = kt * 16 + (lane & 3) * 2;
        uint4 v;
        v.x = pack_f16x2(getW1c(Ww, Wb, nw, k0),     getW1c(Ww, Wb, nw, k0 + 1));
        v.y = pack_f16x2(getW1c(Ww, Wb, nw, k0 + 8), getW1c(Ww, Wb, nw, k0 + 9));
        v.z = pack_f16x2(getW1c(Ww, Wb, nb, k0),     getW1c(Ww, Wb, nb, k0 + 1));
        v.w = pack_f16x2(getW1c(Ww, Wb, nb, k0 + 8), getW1c(Ww, Wb, nb, k0 + 9));
        ((uint4*)(gp + OFF_B1))[idx] = v;
    }
    // B0 frags
    for (int idx = tid; idx < 4 * 4 * 32; idx += 256) {
        int lane = idx & 31, t = idx >> 5;
        int kt = t & 3, nt = t >> 2;
        int n = nt * 8 + (lane >> 2);
        int k0 = kt * 16 + (lane & 3) * 2;
        uint2 v;
        v.x = pack_f16x2(W0[n * 64 + k0],     W0[n * 64 + k0 + 1]);
        v.y = pack_f16x2(W0[n * 64 + k0 + 8], W0[n * 64 + k0 + 9]);
        ((uint2*)(gp + OFF_B0))[idx] = v;
    }
    // B1b frags
    for (int idx = tid; idx < 4 * 2 * 32; idx += 256) {
        int lane = idx & 31, t = idx >> 5;
        int kt = t & 1, nt = t >> 1;
        int n = nt * 8 + (lane >> 2);
        int k0 = kt * 16 + (lane & 3) * 2;
        uint2 v;
        v.x = pack_f16x2(W1[n * 32 + k0],     W1[n * 32 + k0 + 1]);
        v.y = pack_f16x2(W1[n * 32 + k0 + 8], W1[n * 32 + k0 + 9]);
        ((uint2*)(gp + OFF_B1B))[idx] = v;
    }
    // bias / W2 frags (fp32)
    for (int idx = tid; idx < 4 * 32; idx += 256) {
        int lane = idx & 31, j = idx >> 5;
        int c = j * 8 + (lane & 3) * 2;
        float4 bf; bf.x = bw[c]; bf.y = bw[c + 1]; bf.z = bb[c]; bf.w = bb[c + 1];
        ((float4*)(gp + OFF_BIAS1))[idx] = bf;
        float2 f0; f0.x = b0[c]; f0.y = b0[c + 1];
        ((float2*)(gp + OFF_B0F))[idx] = f0;
        float2 f1; f1.x = b1[c]; f1.y = b1[c + 1];
        ((float2*)(gp + OFF_B1F))[idx] = f1;
        float4 w2; w2.x = W2[c]; w2.y = W2[c + 1]; w2.z = W2[32 + c]; w2.w = W2[32 + c + 1];
        ((float4*)(gp + OFF_W2F))[idx] = w2;
    }
    if (tid == 0) *((float*)(gp + OFF_B2)) = b2[0];
}

// ======================= main fused kernel =======================
// 192 threads (6 warps), 192 rows/CTA, SINGLE staging phase.
// Each warp processes TWO m16 tiles: rows warp*32 + mi*16 + {q, q+8}, mi in {0,1}.
// Plane: fp16, 192 rows x 120 halves (stride 60 words = 240 B).
//   A-frag LDS.32 bank = (28q + qp) mod 32 -> exact 32-bank bijection, conflict-free.
// smem: [pack 26640][plane 46080][spov 768] = 73504 B -> 3 CTAs/SM (18 warps)
#define NT 192
#define ROWS_CTA 192
#define PRW 60                                        // plane row stride in words
#define OFF_PLANE  PACK_BYTES                         // 26640
#define OFF_POV    (OFF_PLANE + ROWS_CTA * PRW * 4)   // 72720
#define SMEM_BYTES (OFF_POV + ROWS_CTA * 4 + 16)      // 73504

__global__ void __launch_bounds__(NT, 3)
nnue_main(const float* __restrict__ pov, const float* __restrict__ white,
          const float* __restrict__ black, float* __restrict__ out, int Btot)
{
    extern __shared__ __align__(16) unsigned char smem[];
    unsigned char* packS = smem;
    uint32_t* planeW = (uint32_t*)(smem + OFF_PLANE);
    __half*   planeH = (__half*)planeW;
    float*    spov   = (float*)(smem + OFF_POV);

    const int tid  = threadIdx.x;
    const int warp = tid >> 5;
    const int lane = tid & 31;
    const int q    = lane >> 2;
    const int qp   = lane & 3;
    const long long cbase = (long long)blockIdx.x * ROWS_CTA;

    // ---- copy weight pack into smem ----
    {
        const uint4* src = (const uint4*)g_pack;
        uint4* dst = (uint4*)packS;
        #pragma unroll 4
        for (int i = tid; i < PACK_BYTES / 16; i += NT) dst[i] = src[i];
    }
    spov[tid] = (cbase + tid < (long long)Btot) ? __ldcs(pov + cbase + tid) : 0.f;

    // ---- zero pad words 49..59 of every row ----
    for (int i = tid; i < ROWS_CTA * 11; i += NT) {
        int s = i / 11, w = i - s * 11;
        planeW[s * PRW + 49 + w] = 0u;
    }
    // ---- stage 192 rows as fp16 (coalesced float4 LDG, STS.16) ----
    if (cbase + ROWS_CTA <= (long long)Btot) {
        const float4* gw = (const float4*)(white + cbase * 49);
        const float4* gb = (const float4*)(black + cbase * 49);
        #pragma unroll 2
        for (int i = tid; i < 2352; i += NT) {   // 192*49/4
            float4 v = __ldcs(gw + i);
            int g = 4 * i;
            #pragma unroll
            for (int e = 0; e < 4; e++) {
                int gg = g + e;
                int s = gg / 49, c = gg - s * 49;
                float val = (e == 0) ? v.x : (e == 1) ? v.y : (e == 2) ? v.z : v.w;
                planeH[s * 120 + c] = __float2half(val);
            }
            float4 u = __ldcs(gb + i);
            #pragma unroll
            for (int e = 0; e < 4; e++) {
                int gg = g + e;
                int s = gg / 49, c = gg - s * 49;
                float val = (e == 0) ? u.x : (e == 1) ? u.y : (e == 2) ? u.z : u.w;
                planeH[s * 120 + 49 + c] = __float2half(val);
            }
        }
    } else {
        for (int i = tid; i < ROWS_CTA * 49; i += NT) {
            int s = i / 49, c = i - s * 49;
            long long row = cbase + s;
            bool ok = row < (long long)Btot;
            planeH[s * 120 + c]      = __float2half(ok ? white[row * 49 + c] : 0.f);
            planeH[s * 120 + 49 + c] = __float2half(ok ? black[row * 49 + c] : 0.f);
        }
    }
    __syncthreads();   // the only CTA-wide barrier

    const uint4*  B1u  = (const uint4*)(packS + OFF_B1);
    const uint2*  B0u  = (const uint2*)(packS + OFF_B0);
    const uint2*  B1bu = (const uint2*)(packS + OFF_B1B);
    const float4* bia1 = (const float4*)(packS + OFF_BIAS1);
    const float2* b0f  = (const float2*)(packS + OFF_B0F);
    const float2* b1f  = (const float2*)(packS + OFF_B1F);
    const float4* w2f  = (const float4*)(packS + OFF_W2F);

    const int rbase = warp * 32;   // this warp owns rows rbase..rbase+31 (two m16 tiles)

    #pragma unroll 1
    for (int mi = 0; mi < 2; mi++) {
        const int trow = rbase + mi * 16 + q;   // local row for this tile
        const int rw0 = trow * PRW;
        const int rw1 = rw0 + 8 * PRW;

        // ================= layer 1: single-digit fp16 A, pure LDS.32 =================
        float cw[4][4], cb[4][4];
        #pragma unroll
        for (int j = 0; j < 4; j++)
            #pragma unroll
            for (int i = 0; i < 4; i++) { cw[j][i] = 0.f; cb[j][i] = 0.f; }

        #pragma unroll
        for (int kt = 0; kt < 7; kt++) {
            const int wi = 8 * kt + qp;
            uint32_t ah[4];
            ah[0] = planeW[rw0 + wi];
            ah[1] = planeW[rw1 + wi];
            ah[2] = planeW[rw0 + wi + 4];
            ah[3] = planeW[rw1 + wi + 4];
            #pragma unroll
            for (int j = 0; j < 4; j++) {
                uint4 Bq = B1u[(j * 7 + kt) * 32 + lane];
                mmaf16(cw[j], ah, Bq.x, Bq.y);
                mmaf16(cb[j], ah, Bq.z, Bq.w);
            }
        }

        // ---- epilogue 1: bias + pov mix + relu -> layer-0 A frags (2-digit) ----
        float pv0 = spov[trow];
        float pv1 = spov[trow + 8];
        float pm0 = 1.f - pv0, pm1 = 1.f - pv1;

        uint32_t a0h[4][4], a0l[4][4];
        #pragma unroll
        for (int j = 0; j < 4; j++) {
            float4 bi = bia1[j * 32 + lane];
            float w0 = cw[j][0] + bi.x, w1 = cw[j][1] + bi.y;
            float w2_ = cw[j][2] + bi.x, w3 = cw[j][3] + bi.y;
            float bb0 = cb[j][0] + bi.z, bb1 = cb[j][1] + bi.w;
            float bb2 = cb[j][2] + bi.z, bb3 = cb[j][3] + bi.w;
            float vA0 = fmaxf(fmaf(pv0, w0, pm0 * bb0), 0.f);
            float vA1 = fmaxf(fmaf(pv0, w1, pm0 * bb1), 0.f);
            float vA2 = fmaxf(fmaf(pv1, w2_, pm1 * bb2), 0.f);
            float vA3 = fmaxf(fmaf(pv1, w3, pm1 * bb3), 0.f);
            float vB0 = fmaxf(fmaf(pv0, bb0, pm0 * w0), 0.f);
            float vB1 = fmaxf(fmaf(pv0, bb1, pm0 * w1), 0.f);
            float vB2 = fmaxf(fmaf(pv1, bb2, pm1 * w2_), 0.f);
            float vB3 = fmaxf(fmaf(pv1, bb3, pm1 * w3), 0.f);
            int ktw = j >> 1;
            int pos = (j & 1) ? 2 : 0;
            split_f16_pair(vA0, vA1, a0h[ktw][pos],     a0l[ktw][pos]);
            split_f16_pair(vA2, vA3, a0h[ktw][pos + 1], a0l[ktw][pos + 1]);
            split_f16_pair(vB0, vB1, a0h[ktw + 2][pos],     a0l[ktw + 2][pos]);
            split_f16_pair(vB2, vB3, a0h[ktw + 2][pos + 1], a0l[ktw + 2][pos + 1]);
        }

        // ---- layer 0 (2-pass fp16) ----
        float xv[4][4];
        uint32_t a1h[2][4], a1l[2][4];
        #pragma unroll
        for (int n = 0; n < 4; n++) {
            float c0v[4] = {0.f, 0.f, 0.f, 0.f};
            #pragma unroll
            for (int kt = 0; kt < 4; kt++) {
                uint2 Bq = B0u[(n * 4 + kt) * 32 + lane];
                mmaf16(c0v, a0h[kt], Bq.x, Bq.y);
                mmaf16(c0v, a0l[kt], Bq.x, Bq.y);
            }
            float2 bz = b0f[n * 32 + lane];
            float x0 = fmaxf(c0v[0] + bz.x, 0.f);
            float x1 = fmaxf(c0v[1] + bz.y, 0.f);
            float x2 = fmaxf(c0v[2] + bz.x, 0.f);
            float x3 = fmaxf(c0v[3] + bz.y, 0.f);
            xv[n][0] = x0; xv[n][1] = x1; xv[n][2] = x2; xv[n][3] = x3;
            int ktw = n >> 1;
            int pos = (n & 1) ? 2 : 0;
            split_f16_pair(x0, x1, a1h[ktw][pos],     a1l[ktw][pos]);
            split_f16_pair(x2, x3, a1h[ktw][pos + 1], a1l[ktw][pos + 1]);
        }

        // ---- layer 1b (2-pass fp16) + final dot ----
        float rA = 0.f, rB = 0.f;
        #pragma unroll
        for (int n = 0; n < 4; n++) {
            float c1[4] = {0.f, 0.f, 0.f, 0.f};
            #pragma unroll
            for (int kt = 0; kt < 2; kt++) {
                uint2 Bq = B1bu[(n * 2 + kt) * 32 + lane];
                mmaf16(c1, a1h[kt], Bq.x, Bq.y);
                mmaf16(c1, a1l[kt], Bq.x, Bq.y);
            }
            float2 bz = b1f[n * 32 + lane];
            float y0 = fmaxf(c1[0] + bz.x, 0.f);
            float y1 = fmaxf(c1[1] + bz.y, 0.f);
            float y2 = fmaxf(c1[2] + bz.x, 0.f);
            float y3 = fmaxf(c1[3] + bz.y, 0.f);
            float4 w2 = w2f[n * 32 + lane];
            rA = fmaf(w2.x, xv[n][0], rA); rA = fmaf(w2.y, xv[n][1], rA);
            rA = fmaf(w2.z, y0, rA);       rA = fmaf(w2.w, y1, rA);
            rB = fmaf(w2.x, xv[n][2], rB); rB = fmaf(w2.y, xv[n][3], rB);
            rB = fmaf(w2.z, y2, rB);       rB = fmaf(w2.w, y3, rB);
        }
        rA += __shfl_xor_sync(0xFFFFFFFFu, rA, 1);
        rA += __shfl_xor_sync(0xFFFFFFFFu, rA, 2);
        rB += __shfl_xor_sync(0xFFFFFFFFu, rB, 1);
        rB += __shfl_xor_sync(0xFFFFFFFFu, rB, 2);
        if (qp == 0) {
            const float b2v = *((const float*)(packS + OFF_B2));
            long long rowA = cbase + trow;
            long long rowB = rowA + 8;
            if (rowA < (long long)Btot) out[rowA] = rA + b2v;
            if (rowB < (long long)Btot) out[rowB] = rB + b2v;
        }
    }
}

// ======================= launch =======================
extern "C" void kernel_launch(void* const* d_in, const int* in_sizes, int n_in,
                              void* d_out, int out_size) {
    const float* pov   = (const float*)d_in[0];
    const float* white = (const float*)d_in[1];
    const float* black = (const float*)d_in[2];
    const float* Ww = (const float*)d_in[3];
    const float* bw = (const float*)d_in[4];
    const float* Wb = (const float*)d_in[5];
    const float* bb = (const float*)d_in[6];
    const float* W0 = (const float*)d_in[7];
    const float* b0 = (const float*)d_in[8];
    const float* W1 = (const float*)d_in[9];
    const float* b1 = (const float*)d_in[10];
    const float* W2 = (const float*)d_in[11];
    const float* b2 = (const float*)d_in[12];
    const int B = in_sizes[0];

    prep_kernel<<<1, 256>>>(Ww, Wb, W0, W1, bw, bb, b0, b1, W2, b2);

    cudaFuncSetAttribute(nnue_main, cudaFuncAttributeMaxDynamicSharedMemorySize, SMEM_BYTES);
    int grid = (B + ROWS_CTA - 1) / ROWS_CTA;
    nnue_main<<<grid, NT, SMEM_BYTES>>>(pov, white, black, (float*)d_out, B);
}